// round 16
// baseline (speedup 1.0000x reference)
#include <cuda_runtime.h>
#include <cuda_bf16.h>
#include <math.h>
#include <cstdint>

// ---------------- problem constants ----------------
#define Bb        2
#define LSEQ      2048
#define TTOK      4096
#define DMODEL    2048
#define DINNER    4096
#define NHEAD     64
#define DHEAD     64
#define NSTATE    128
#define NGRP      8
#define CHUNK     256
#define NCHUNK    8
#define GN        1024
#define CONVDIM   6144
#define INPROJ    10304
#define INPROJ_PAD 10368          // 81*128
#define COL_ADT   4096
#define COL_GATE  6208
#define CCOL_B    4096
#define CCOL_C    5120

#define OUT_ELEMS   (TTOK*DMODEL)
#define HFIN_ELEMS  (Bb*NHEAD*NSTATE*DHEAD)

// ---------------- scratch (device globals; device-code refs ONLY) -------------
__device__ float g_proj[(size_t)TTOK*INPROJ];
__device__ float g_conv[(size_t)TTOK*CONVDIM];
__device__ float g_A[(size_t)TTOK*NHEAD];
__device__ float g_Alast[Bb*NCHUNK*NHEAD];
__device__ float g_states[(size_t)Bb*NCHUNK*NHEAD*NSTATE*DHEAD];
__device__ float g_hprev[(size_t)Bb*NCHUNK*NHEAD*NSTATE*DHEAD];
__device__ float g_Y[(size_t)TTOK*DINNER];
__device__ float g_CB[(size_t)Bb*NCHUNK*NGRP*CHUNK*CHUNK];
// split operands, layout [hi | lo], row stride 2K
__device__ __nv_bfloat16 g_a2[(size_t)TTOK*2*DINNER];
__device__ __nv_bfloat16 g_b2in[(size_t)INPROJ_PAD*2*DMODEL];
__device__ __nv_bfloat16 g_b2out[(size_t)DMODEL*2*DINNER];

// ---------------- helpers ----------------
__device__ __forceinline__ float block_reduce_sum_256(float v) {
    __shared__ float red[8];
    int lane = threadIdx.x & 31, w = threadIdx.x >> 5;
    #pragma unroll
    for (int o = 16; o; o >>= 1) v += __shfl_xor_sync(0xffffffffu, v, o);
    if (lane == 0) red[w] = v;
    __syncthreads();
    if (w == 0) {
        v = (lane < 8) ? red[lane] : 0.f;
        #pragma unroll
        for (int o = 4; o; o >>= 1) v += __shfl_xor_sync(0xffffffffu, v, o);
        if (lane == 0) red[0] = v;
    }
    __syncthreads();
    return red[0];
}

__device__ __forceinline__ unsigned int s2u(const void* p) {
    unsigned int a;
    asm("{ .reg .u64 t; cvta.to.shared.u64 t, %1; cvt.u32.u64 %0, t; }" : "=r"(a) : "l"(p));
    return a;
}

__device__ __forceinline__ void cpa16(unsigned int d, const void* g) {
    asm volatile("cp.async.cg.shared.global [%0], [%1], 16;\n" :: "r"(d), "l"(g));
}

// parallel inclusive scan of 256 values (one per thread)
__device__ __forceinline__ float scan256(float a, float* wps, float* tot) {
    int lane = threadIdx.x & 31, w = threadIdx.x >> 5;
    #pragma unroll
    for (int o = 1; o < 32; o <<= 1) {
        float t = __shfl_up_sync(0xffffffffu, a, o);
        if (lane >= o) a += t;
    }
    if (lane == 31) wps[w] = a;
    __syncthreads();
    if (threadIdx.x == 0) {
        float s = 0.f;
        #pragma unroll
        for (int j = 0; j < 8; j++) { float t = wps[j]; wps[j] = s; s += t; }
        wps[8] = s;
    }
    __syncthreads();
    float r = a + wps[w];
    *tot = wps[8];
    return r;
}

// ---------------- K1: input rmsnorm + bf16 split ([hi|lo]) --------------------
__global__ __launch_bounds__(256) void k_rms_in(const float* __restrict__ x,
                                                const float* __restrict__ w) {
    int row = blockIdx.x;
    const float* xr = x + (size_t)row * DMODEL;
    float vloc[8];
    float ss = 0.f;
    #pragma unroll
    for (int j = 0; j < 8; j++) { float v = xr[threadIdx.x + j * 256]; vloc[j] = v; ss += v * v; }
    float tot = block_reduce_sum_256(ss);
    float r = rsqrtf(tot * (1.f / DMODEL) + 1e-6f);
    size_t base = (size_t)row * (2 * DMODEL);
    #pragma unroll
    for (int j = 0; j < 8; j++) {
        int k = threadIdx.x + j * 256;
        float v = vloc[j] * r * w[k];
        __nv_bfloat16 hi = __float2bfloat16(v);
        __nv_bfloat16 lo = __float2bfloat16(v - __bfloat162float(hi));
        g_a2[base + k] = hi;
        g_a2[base + DMODEL + k] = lo;
    }
}

// ---------------- weight split conversion ([hi|lo]), 4 elems/thread -----------
__global__ __launch_bounds__(256) void k_cvt(int dsel, const float* __restrict__ srcp,
                                             int R, int K) {
    __nv_bfloat16* dst = (dsel == 1) ? g_b2in : g_b2out;
    int K4 = K >> 2;
    size_t idx = (size_t)blockIdx.x * 256 + threadIdx.x;
    int row = (int)(idx / K4);
    int k = (int)(idx - (size_t)row * K4) * 4;
    float4 v = (row < R) ? *(const float4*)&srcp[(size_t)row * K + k]
                         : make_float4(0.f, 0.f, 0.f, 0.f);
    __nv_bfloat16 hi[4], lo[4];
    float vv[4] = {v.x, v.y, v.z, v.w};
    #pragma unroll
    for (int j = 0; j < 4; j++) {
        hi[j] = __float2bfloat16(vv[j]);
        lo[j] = __float2bfloat16(vv[j] - __bfloat162float(hi[j]));
    }
    size_t base = (size_t)row * (2 * (size_t)K);
    *(uint2*)&dst[base + k]     = *(uint2*)hi;
    *(uint2*)&dst[base + K + k] = *(uint2*)lo;
}

// ---------------- bf16 tensor-core GEMM with fragment-reuse split -------------
// C[M,N] = sum over k of (Ahi+Alo)*(Bhi+Blo) dropping lo*lo.
// Operands stored [hi|lo] with row stride 2K; K here is the ORIGINAL depth.
#define HG_TILE  (128 * 40)
#define HG_STAGE (4 * HG_TILE)
#define HG_SMEM  (2 * HG_STAGE * 2)    // 81920 bytes

__global__ __launch_bounds__(256, 2) void k_hgemm(int selb, int selc,
        float* __restrict__ Cout,
        const float* __restrict__ addend, int M, int N, int K) {
    extern __shared__ __nv_bfloat16 smp[];
    const __nv_bfloat16* A2 = g_a2;
    const __nv_bfloat16* B2 = selb ? g_b2out : g_b2in;
    float* C = selc ? Cout : g_proj;
    int K2 = 2 * K;

    int tid = threadIdx.x, lane = tid & 31, warp = tid >> 5;
    int wm = warp >> 2, wn = warp & 3;
    int m0 = blockIdx.y * 128, n0 = blockIdx.x * 128;

    float acc[4][4][4];
    #pragma unroll
    for (int mi = 0; mi < 4; mi++)
        #pragma unroll
        for (int ni = 0; ni < 4; ni++)
            #pragma unroll
            for (int q = 0; q < 4; q++) acc[mi][ni][q] = 0.f;

    int nK = K >> 5;

    auto issue = [&](int kt, int st) {
        __nv_bfloat16* Ah = smp + st * HG_STAGE;
        __nv_bfloat16* Al = Ah + HG_TILE;
        __nv_bfloat16* Bh = Al + HG_TILE;
        __nv_bfloat16* Bl = Bh + HG_TILE;
        size_t kk = (size_t)kt * 32;
        #pragma unroll
        for (int i = 0; i < 2; i++) {
            int idx = tid + i * 256;
            int row = idx >> 2, c8 = (idx & 3) * 8;
            const __nv_bfloat16* ap = &A2[(size_t)(m0 + row) * K2 + kk + c8];
            const __nv_bfloat16* bp = &B2[(size_t)(n0 + row) * K2 + kk + c8];
            cpa16(s2u(&Ah[row * 40 + c8]), ap);
            cpa16(s2u(&Al[row * 40 + c8]), ap + K);
            cpa16(s2u(&Bh[row * 40 + c8]), bp);
            cpa16(s2u(&Bl[row * 40 + c8]), bp + K);
        }
        asm volatile("cp.async.commit_group;\n" ::);
    };

    issue(0, 0);

    for (int kt = 0; kt < nK; kt++) {
        int buf = kt & 1;
        if (kt + 1 < nK) {
            issue(kt + 1, (kt + 1) & 1);
            asm volatile("cp.async.wait_group 1;\n" ::);
        } else {
            asm volatile("cp.async.wait_group 0;\n" ::);
        }
        __syncthreads();

        const __nv_bfloat16* Ah = smp + buf * HG_STAGE;
        const __nv_bfloat16* Al = Ah + HG_TILE;
        const __nv_bfloat16* Bh = Al + HG_TILE;
        const __nv_bfloat16* Bl = Bh + HG_TILE;

        #pragma unroll
        for (int kh = 0; kh < 2; kh++) {
            unsigned int bh[4][2], bl[4][2];
            int bro = (wn * 32 + (lane & 7)) * 40 + kh * 16 + ((lane >> 3) & 1) * 8;
            #pragma unroll
            for (int ni = 0; ni < 4; ni++) {
                unsigned int addr = s2u(&Bh[bro + ni * 8 * 40]);
                asm volatile("ldmatrix.sync.aligned.m8n8.x2.shared.b16 {%0,%1}, [%2];"
                    : "=r"(bh[ni][0]), "=r"(bh[ni][1]) : "r"(addr));
                addr = s2u(&Bl[bro + ni * 8 * 40]);
                asm volatile("ldmatrix.sync.aligned.m8n8.x2.shared.b16 {%0,%1}, [%2];"
                    : "=r"(bl[ni][0]), "=r"(bl[ni][1]) : "r"(addr));
            }
            int aro = (wm * 64 + (lane & 15)) * 40 + kh * 16 + (lane >> 4) * 8;
            #pragma unroll
            for (int mi = 0; mi < 4; mi++) {
                unsigned int ah[4], al[4];
                unsigned int addr = s2u(&Ah[aro + mi * 16 * 40]);
                asm volatile("ldmatrix.sync.aligned.m8n8.x4.shared.b16 {%0,%1,%2,%3}, [%4];"
                    : "=r"(ah[0]), "=r"(ah[1]), "=r"(ah[2]), "=r"(ah[3]) : "r"(addr));
                #pragma unroll
                for (int ni = 0; ni < 4; ni++)
                    asm volatile("mma.sync.aligned.m16n8k16.row.col.f32.bf16.bf16.f32 "
                        "{%0,%1,%2,%3},{%4,%5,%6,%7},{%8,%9},{%0,%1,%2,%3};"
                        : "+f"(acc[mi][ni][0]), "+f"(acc[mi][ni][1]),
                          "+f"(acc[mi][ni][2]), "+f"(acc[mi][ni][3])
                        : "r"(ah[0]), "r"(ah[1]), "r"(ah[2]), "r"(ah[3]),
                          "r"(bh[ni][0]), "r"(bh[ni][1]));
                #pragma unroll
                for (int ni = 0; ni < 4; ni++)
                    asm volatile("mma.sync.aligned.m16n8k16.row.col.f32.bf16.bf16.f32 "
                        "{%0,%1,%2,%3},{%4,%5,%6,%7},{%8,%9},{%0,%1,%2,%3};"
                        : "+f"(acc[mi][ni][0]), "+f"(acc[mi][ni][1]),
                          "+f"(acc[mi][ni][2]), "+f"(acc[mi][ni][3])
                        : "r"(ah[0]), "r"(ah[1]), "r"(ah[2]), "r"(ah[3]),
                          "r"(bl[ni][0]), "r"(bl[ni][1]));
                addr = s2u(&Al[aro + mi * 16 * 40]);
                asm volatile("ldmatrix.sync.aligned.m8n8.x4.shared.b16 {%0,%1,%2,%3}, [%4];"
                    : "=r"(al[0]), "=r"(al[1]), "=r"(al[2]), "=r"(al[3]) : "r"(addr));
                #pragma unroll
                for (int ni = 0; ni < 4; ni++)
                    asm volatile("mma.sync.aligned.m16n8k16.row.col.f32.bf16.bf16.f32 "
                        "{%0,%1,%2,%3},{%4,%5,%6,%7},{%8,%9},{%0,%1,%2,%3};"
                        : "+f"(acc[mi][ni][0]), "+f"(acc[mi][ni][1]),
                          "+f"(acc[mi][ni][2]), "+f"(acc[mi][ni][3])
                        : "r"(al[0]), "r"(al[1]), "r"(al[2]), "r"(al[3]),
                          "r"(bh[ni][0]), "r"(bh[ni][1]));
            }
        }
        __syncthreads();
    }

    // epilogue: paired float2 access (N even; cc even => cc<N implies cc+1<N)
    #pragma unroll
    for (int mi = 0; mi < 4; mi++) {
        int r = m0 + wm * 64 + mi * 16 + (lane >> 2);
        #pragma unroll
        for (int ni = 0; ni < 4; ni++) {
            int cc = n0 + wn * 32 + ni * 8 + (lane & 3) * 2;
            if (cc < N) {
                #pragma unroll
                for (int half = 0; half < 2; half++) {
                    int rr = r + half * 8;
                    float2 v = make_float2(acc[mi][ni][half * 2], acc[mi][ni][half * 2 + 1]);
                    if (addend) {
                        float2 a = *(const float2*)&addend[(size_t)rr * N + cc];
                        v.x += a.x; v.y += a.y;
                    }
                    *(float2*)&C[(size_t)rr * N + cc] = v;
                }
            }
        }
    }
}

// ---------------- K3: depthwise conv4 + bias + rmsnorm + silu (scalar) --------
__global__ __launch_bounds__(256) void k_conv(const float* __restrict__ cw,
        const float* __restrict__ cb, const float* __restrict__ cnw) {
    int t = blockIdx.x;
    int b = t >> 11, l = t & 2047;
    float v[24];
    float ss = 0.f;
    #pragma unroll
    for (int j = 0; j < 24; j++) {
        int c = threadIdx.x + j * 256;
        int pc = (c < DINNER) ? c : c + NHEAD;
        float a = cb[c];
        #pragma unroll
        for (int k = 0; k < 4; k++) {
            int lk = l + k - 3;
            if (lk >= 0)
                a += cw[c * 4 + k] * g_proj[(size_t)(b * LSEQ + lk) * INPROJ + pc];
        }
        v[j] = a;
        ss += a * a;
    }
    float tot = block_reduce_sum_256(ss);
    float r = rsqrtf(tot * (1.f / CONVDIM) + 1e-6f);
    #pragma unroll
    for (int j = 0; j < 24; j++) {
        int c = threadIdx.x + j * 256;
        float y = v[j] * r * cnw[c];
        g_conv[(size_t)t * CONVDIM + c] = y / (1.f + expf(-y));
    }
}

// ---------------- K4: dt path ----------------
__global__ __launch_bounds__(256) void k_dt(const float* __restrict__ dt_w,
        const float* __restrict__ dt_b, const float* __restrict__ A_log) {
    __shared__ float ad[4][64];
    int sub = threadIdx.x >> 6, h = threadIdx.x & 63;
    int t = blockIdx.x * 4 + sub;
    ad[sub][h] = g_proj[(size_t)t * INPROJ + COL_ADT + h];
    __syncthreads();
    float z = dt_b[h];
    #pragma unroll
    for (int k = 0; k < 64; k++) z += ad[sub][k] * dt_w[h * 64 + k];
    float dt = (z > 20.f) ? z : log1pf(expf(z));
    g_A[(size_t)t * NHEAD + h] = -expf(A_log[h]) * dt;
}

// ---------------- K5: per-chunk states ----------------------------------------
__global__ __launch_bounds__(256) void k_states() {
    __shared__ __align__(16) float sB[32 * 128];
    __shared__ __align__(16) float sX[32 * 64];
    __shared__ float sw[256];
    __shared__ float wps[9];
    int blk = blockIdx.x;
    int b = blk >> 9, c = (blk >> 6) & 7, h = blk & 63, g = h >> 3;
    int tid = threadIdx.x;
    size_t tokbase = (size_t)(b * LSEQ + c * CHUNK);

    float av = g_A[(tokbase + tid) * NHEAD + h];
    float atot;
    float acs = scan256(av, wps, &atot);
    sw[tid] = expf(atot - acs);
    if (tid == 0) g_Alast[blk] = atot;
    __syncthreads();

    int n = tid >> 1, dh = tid & 1, db = dh << 5;
    float acc[32];
    #pragma unroll
    for (int j = 0; j < 32; j++) acc[j] = 0.f;

    for (int t0 = 0; t0 < 256; t0 += 32) {
        __syncthreads();
        #pragma unroll
        for (int k = 0; k < 4; k++) {
            int q = tid + k * 256; int j = q >> 5, n4 = (q & 31) << 2;
            *(float4*)&sB[j * 128 + n4] =
                *(const float4*)&g_conv[(tokbase + t0 + j) * CONVDIM + CCOL_B + g * 128 + n4];
        }
        #pragma unroll
        for (int k = 0; k < 2; k++) {
            int q = tid + k * 256; int j = q >> 4, d4 = (q & 15) << 2;
            *(float4*)&sX[j * 64 + d4] =
                *(const float4*)&g_conv[(tokbase + t0 + j) * CONVDIM + h * 64 + d4];
        }
        __syncthreads();
        #pragma unroll
        for (int i = 0; i < 32; i++) {
            float bw = sB[i * 128 + n] * sw[t0 + i];
            const float4* xr = (const float4*)&sX[i * 64 + db];
            #pragma unroll
            for (int j = 0; j < 8; j++) {
                float4 xv = xr[j];
                acc[4 * j + 0] += bw * xv.x;
                acc[4 * j + 1] += bw * xv.y;
                acc[4 * j + 2] += bw * xv.z;
                acc[4 * j + 3] += bw * xv.w;
            }
        }
    }
    size_t ob = ((size_t)blk * NSTATE + n) * DHEAD + db;
    #pragma unroll
    for (int j = 0; j < 8; j++)
        *(float4*)&g_states[ob + 4 * j] =
            make_float4(acc[4 * j], acc[4 * j + 1], acc[4 * j + 2], acc[4 * j + 3]);
}

// ---------------- K6: inter-chunk scan -----------------------------------------
__global__ __launch_bounds__(256) void k_scan(float* __restrict__ hout) {
    int b = blockIdx.x >> 6, h = blockIdx.x & 63;
    int e0 = threadIdx.x * 32;
    float hs[32];
    #pragma unroll
    for (int j = 0; j < 32; j++) hs[j] = 0.f;
    for (int c = 0; c < NCHUNK; c++) {
        int chb = (b * NCHUNK + c) * NHEAD + h;
        float cd = expf(g_Alast[chb]);
        size_t base = (size_t)chb * (NSTATE * DHEAD) + e0;
        #pragma unroll
        for (int j = 0; j < 8; j++) {
            *(float4*)&g_hprev[base + 4 * j] =
                make_float4(hs[4 * j], hs[4 * j + 1], hs[4 * j + 2], hs[4 * j + 3]);
            float4 st = *(const float4*)&g_states[base + 4 * j];
            hs[4 * j + 0] = hs[4 * j + 0] * cd + st.x;
            hs[4 * j + 1] = hs[4 * j + 1] * cd + st.y;
            hs[4 * j + 2] = hs[4 * j + 2] * cd + st.z;
            hs[4 * j + 3] = hs[4 * j + 3] * cd + st.w;
        }
    }
    if (hout) {
        size_t ob = (size_t)(b * NHEAD + h) * (NSTATE * DHEAD) + e0;
        #pragma unroll
        for (int j = 0; j < 8; j++)
            *(float4*)&hout[ob + 4 * j] =
                make_float4(hs[4 * j], hs[4 * j + 1], hs[4 * j + 2], hs[4 * j + 3]);
    }
}

// ---------------- K-CB: per-(b,c,g) raw CB = C @ B^T (tril tiles) --------------
__global__ __launch_bounds__(256) void k_cb() {
    __shared__ __align__(16) float sCt[32][128];
    __shared__ __align__(16) float sB[32 * 133];
    int blk = blockIdx.x;
    int b = blk >> 6, c = (blk >> 3) & 7, g = blk & 7;
    int tid = threadIdx.x;
    size_t tokbase = (size_t)(b * LSEQ + c * CHUNK);
    size_t cbbase = (size_t)blk * (CHUNK * CHUNK);
    int bi = tid >> 4, bj = tid & 15;

    for (int t0 = 0; t0 < 8; t0++) {
        __syncthreads();
        #pragma unroll
        for (int k = 0; k < 4; k++) {
            int q = tid + k * 256; int i = q >> 5, n4 = (q & 31) << 2;
            *(float4*)&sCt[i][n4] =
                *(const float4*)&g_conv[(tokbase + t0 * 32 + i) * CONVDIM + CCOL_C + g * 128 + n4];
        }
        for (int s0 = 0; s0 <= t0; s0++) {
            __syncthreads();
            #pragma unroll
            for (int k = 0; k < 4; k++) {
                int q = tid + k * 256; int j = q >> 5, n4 = (q & 31) << 2;
                float4 v = *(const float4*)&g_conv[(tokbase + s0 * 32 + j) * CONVDIM + CCOL_B + g * 128 + n4];
                sB[j * 133 + n4 + 0] = v.x;
                sB[j * 133 + n4 + 1] = v.y;
                sB[j * 133 + n4 + 2] = v.z;
                sB[j * 133 + n4 + 3] = v.w;
            }
            __syncthreads();
            float m00 = 0.f, m01 = 0.f, m10 = 0.f, m11 = 0.f;
            const float* c0p = &sCt[2 * bi][0];
            const float* c1p = &sCt[2 * bi + 1][0];
            const float* b0p = &sB[(2 * bj) * 133];
            const float* b1p = &sB[(2 * bj + 1) * 133];
            #pragma unroll 8
            for (int n = 0; n < 128; n++) {
                float c0 = c0p[n], c1 = c1p[n], bb0 = b0p[n], bb1 = b1p[n];
                m00 += c0 * bb0; m01 += c0 * bb1;
                m10 += c1 * bb0; m11 += c1 * bb1;
            }
            size_t r0 = cbbase + (size_t)(t0 * 32 + 2 * bi) * CHUNK + s0 * 32 + 2 * bj;
            *(float2*)&g_CB[r0] = make_float2(m00, m01);
            *(float2*)&g_CB[r0 + CHUNK] = make_float2(m10, m11);
        }
    }
}

// ---------------- K7: Y = Y_diag + Y_carry (X cached in dynamic smem) ---------
#define YD_SMEM (CHUNK * DHEAD * 4)   // 65536 bytes: whole chunk's X
__global__ __launch_bounds__(256) void k_ydiag() {
    __shared__ float sAcs[256];
    __shared__ float wps[9];
    __shared__ __align__(16) float sCtT[128][36];
    __shared__ __align__(16) float sM[32][36];
    __shared__ __align__(16) float sH[32 * 64];
    __shared__ float fr[32];
    __shared__ float gc[256];
    extern __shared__ __align__(16) float sXa[];   // [256][64]
    int blk = blockIdx.x;
    int b = blk >> 9, c = (blk >> 6) & 7, h = blk & 63, g = h >> 3;
    int tid = threadIdx.x;
    size_t tokbase = (size_t)(b * LSEQ + c * CHUNK);
    size_t chb = (size_t)blk;
    size_t cbbase = (size_t)(((b * 8 + c) * 8) + g) * (CHUNK * CHUNK);

    {
        float av = g_A[(tokbase + tid) * NHEAD + h];
        float atot;
        float acs = scan256(av, wps, &atot);
        sAcs[tid] = acs;
    }
    // load ALL X tiles for the chunk once: 256 rows x 64 floats
    #pragma unroll
    for (int k = 0; k < 16; k++) {
        int q = tid + k * 256;            // q in [0, 4096): row = q>>4, d4 = (q&15)*4
        int j = q >> 4, d4 = (q & 15) << 2;
        *(float4*)&sXa[j * 64 + d4] =
            *(const float4*)&g_conv[(tokbase + j) * CONVDIM + h * 64 + d4];
    }
    __syncthreads();

    int ty = tid >> 5, tx = tid & 31;
    int bi = tid >> 4, bj = tid & 15;

    for (int t0 = 0; t0 < 8; t0++) {
        __syncthreads();
        #pragma unroll
        for (int k = 0; k < 4; k++) {
            int q = tid + k * 256;
            int chunk = q >> 5, i = q & 31;
            float4 v = *(const float4*)&g_conv[(tokbase + t0 * 32 + i) * CONVDIM + CCOL_C + g * 128 + chunk * 4];
            sCtT[chunk * 4 + 0][i] = v.x;
            sCtT[chunk * 4 + 1][i] = v.y;
            sCtT[chunk * 4 + 2][i] = v.z;
            sCtT[chunk * 4 + 3][i] = v.w;
        }
        float ar = sAcs[t0 * 32];
        if (tid < 32) fr[tid] = expf(sAcs[t0 * 32 + tid] - ar);
        if (tid < t0 * 32) gc[tid] = expf(ar - sAcs[tid]);
        __syncthreads();

        float accD[4][2] = {{0.f,0.f},{0.f,0.f},{0.f,0.f},{0.f,0.f}};
        float acc2[4][2] = {{0.f,0.f},{0.f,0.f},{0.f,0.f},{0.f,0.f}};

        for (int s0 = 0; s0 <= t0; s0++) {
            {
                int i0 = 2 * bi, j0 = 2 * bj;
                size_t r0 = cbbase + (size_t)(t0 * 32 + i0) * CHUNK + s0 * 32 + j0;
                float2 m0 = *(const float2*)&g_CB[r0];
                float2 m1 = *(const float2*)&g_CB[r0 + CHUNK];
                if (s0 < t0) {
                    float f0 = fr[i0], f1 = fr[i0 + 1];
                    float g0 = gc[s0 * 32 + j0], g1 = gc[s0 * 32 + j0 + 1];
                    sM[j0][i0]         = m0.x * f0 * g0;
                    sM[j0 + 1][i0]     = m0.y * f0 * g1;
                    sM[j0][i0 + 1]     = m1.x * f1 * g0;
                    sM[j0 + 1][i0 + 1] = m1.y * f1 * g1;
                } else {
                    float at0 = sAcs[t0 * 32 + i0], at1 = sAcs[t0 * 32 + i0 + 1];
                    float as0 = sAcs[s0 * 32 + j0], as1 = sAcs[s0 * 32 + j0 + 1];
                    sM[j0][i0]         = (j0     <= i0    ) ? m0.x * expf(at0 - as0) : 0.f;
                    sM[j0 + 1][i0]     = (j0 + 1 <= i0    ) ? m0.y * expf(at0 - as1) : 0.f;
                    sM[j0][i0 + 1]     = (j0     <= i0 + 1) ? m1.x * expf(at1 - as0) : 0.f;
                    sM[j0 + 1][i0 + 1] = (j0 + 1 <= i0 + 1) ? m1.y * expf(at1 - as1) : 0.f;
                }
            }
            __syncthreads();
            const float* xrow = &sXa[(size_t)s0 * 32 * 64];
            #pragma unroll
            for (int k = 0; k < 32; k++) {
                float4 mv = *(const float4*)&sM[k][4 * ty];
                float2 xv = *(const float2*)&xrow[k * 64 + 2 * tx];
                accD[0][0] += mv.x * xv.x; accD[0][1] += mv.x * xv.y;
                accD[1][0] += mv.y * xv.x; accD[1][1] += mv.y * xv.y;
                accD[2][0] += mv.z * xv.x; accD[2][1] += mv.z * xv.y;
                accD[3][0] += mv.w * xv.x; accD[3][1] += mv.w * xv.y;
            }
            __syncthreads();
        }
        for (int qh = 0; qh < 4; qh++) {
            #pragma unroll
            for (int k = 0; k < 2; k++) {
                int q = tid + k * 256; int nl = q >> 4, d4 = (q & 15) << 2;
                *(float4*)&sH[nl * 64 + d4] =
                    *(const float4*)&g_hprev[(chb * NSTATE + qh * 32 + nl) * DHEAD + d4];
            }
            __syncthreads();
            #pragma unroll
            for (int k = 0; k < 32; k++) {
                int n = qh * 32 + k;
                float4 cv = *(const float4*)&sCtT[n][4 * ty];
                float2 hv = *(const float2*)&sH[k * 64 + 2 * tx];
                acc2[0][0] += cv.x * hv.x; acc2[0][1] += cv.x * hv.y;
                acc2[1][0] += cv.y * hv.x; acc2[1][1] += cv.y * hv.y;
                acc2[2][0] += cv.z * hv.x; acc2[2][1] += cv.z * hv.y;
                acc2[3][0] += cv.w * hv.x; acc2[3][1] += cv.w * hv.y;
            }
            __syncthreads();
        }
        #pragma unroll
        for (int r = 0; r < 4; r++) {
            int t = t0 * 32 + 4 * ty + r;
            float e = expf(sAcs[t]);
            size_t off = (tokbase + t) * DINNER + h * 64 + 2 * tx;
            g_Y[off]     = accD[r][0] + acc2[r][0] * e;
            g_Y[off + 1] = accD[r][1] + acc2[r][1] * e;
        }
    }
}

// ---------------- K8: out rmsnorm * silu(gate) -> bf16 split into g_a2 --------
__global__ __launch_bounds__(256) void k_gate(const float* __restrict__ onw) {
    int t = blockIdx.x;
    float vloc[16];
    float ss = 0.f;
    #pragma unroll
    for (int j = 0; j < 16; j++) {
        float v = g_Y[(size_t)t * DINNER + threadIdx.x + j * 256];
        vloc[j] = v;
        ss += v * v;
    }
    float tot = block_reduce_sum_256(ss);
    float r = rsqrtf(tot * (1.f / DINNER) + 1e-6f);
    size_t base = (size_t)t * (2 * DINNER);
    #pragma unroll
    for (int j = 0; j < 16; j++) {
        int k = threadIdx.x + j * 256;
        float y = vloc[j] * r * onw[k];
        float gt = g_proj[(size_t)t * INPROJ + COL_GATE + k];
        float v = y * gt / (1.f + expf(-gt));
        __nv_bfloat16 hi = __float2bfloat16(v);
        __nv_bfloat16 lo = __float2bfloat16(v - __bfloat162float(hi));
        g_a2[base + k] = hi;
        g_a2[base + DINNER + k] = lo;
    }
}

// ---------------- launch ----------------
extern "C" void kernel_launch(void* const* d_in, const int* in_sizes, int n_in,
                              void* d_out, int out_size) {
    const float* x          = (const float*)d_in[0];
    const float* norm_w     = (const float*)d_in[1];
    const float* in_proj_w  = (const float*)d_in[2];
    const float* conv_w     = (const float*)d_in[3];
    const float* conv_b     = (const float*)d_in[4];
    const float* conv_norm_w= (const float*)d_in[5];
    const float* A_log      = (const float*)d_in[6];
    const float* dt_w       = (const float*)d_in[7];
    const float* dt_b       = (const float*)d_in[8];
    const float* out_norm_w = (const float*)d_in[9];
    const float* out_proj_w = (const float*)d_in[10];
    float* out = (float*)d_out;

    float* hfin = (out_size >= OUT_ELEMS + HFIN_ELEMS) ? (out + OUT_ELEMS) : nullptr;

    cudaFuncSetAttribute(k_hgemm, cudaFuncAttributeMaxDynamicSharedMemorySize, HG_SMEM);
    cudaFuncSetAttribute(k_ydiag, cudaFuncAttributeMaxDynamicSharedMemorySize, YD_SMEM);

    k_rms_in<<<TTOK, 256>>>(x, norm_w);
    k_cvt<<<(unsigned)(((size_t)INPROJ_PAD * DMODEL) / 1024), 256>>>(1, in_proj_w, INPROJ, DMODEL);
    k_hgemm<<<dim3(INPROJ_PAD / 128, TTOK / 128), 256, HG_SMEM>>>(
        0, 0, nullptr, nullptr, TTOK, INPROJ, DMODEL);

    k_conv<<<TTOK, 256>>>(conv_w, conv_b, conv_norm_w);
    k_dt<<<TTOK / 4, 256>>>(dt_w, dt_b, A_log);
    k_cb<<<Bb * NCHUNK * NGRP, 256>>>();
    k_states<<<Bb * NCHUNK * NHEAD, 256>>>();
    k_scan<<<Bb * NHEAD, 256>>>(hfin);
    k_ydiag<<<Bb * NCHUNK * NHEAD, 256, YD_SMEM>>>();
    k_gate<<<TTOK, 256>>>(out_norm_w);

    k_cvt<<<(unsigned)(((size_t)DMODEL * DINNER) / 1024), 256>>>(2, out_proj_w, DMODEL, DINNER);
    k_hgemm<<<dim3(DMODEL / 128, TTOK / 128), 256, HG_SMEM>>>(
        1, 1, out, x, TTOK, DMODEL, DINNER);
}

// round 17
// speedup vs baseline: 1.0291x; 1.0291x over previous
#include <cuda_runtime.h>
#include <cuda_bf16.h>
#include <math.h>
#include <cstdint>

// ---------------- problem constants ----------------
#define Bb        2
#define LSEQ      2048
#define TTOK      4096
#define DMODEL    2048
#define DINNER    4096
#define NHEAD     64
#define DHEAD     64
#define NSTATE    128
#define NGRP      8
#define CHUNK     256
#define NCHUNK    8
#define GN        1024
#define CONVDIM   6144
#define INPROJ    10304
#define INPROJ_PAD 10368          // 81*128
#define COL_ADT   4096
#define COL_GATE  6208
#define CCOL_B    4096
#define CCOL_C    5120

#define OUT_ELEMS   (TTOK*DMODEL)
#define HFIN_ELEMS  (Bb*NHEAD*NSTATE*DHEAD)

// ---------------- scratch (device globals; device-code refs ONLY) -------------
__device__ float g_proj[(size_t)TTOK*INPROJ];
__device__ float g_conv[(size_t)TTOK*CONVDIM];
__device__ float g_A[(size_t)TTOK*NHEAD];
__device__ float g_Alast[Bb*NCHUNK*NHEAD];
__device__ float g_states[(size_t)Bb*NCHUNK*NHEAD*NSTATE*DHEAD];
__device__ float g_hprev[(size_t)Bb*NCHUNK*NHEAD*NSTATE*DHEAD];
__device__ float g_Y[(size_t)TTOK*DINNER];
__device__ float g_CB[(size_t)Bb*NCHUNK*NGRP*CHUNK*CHUNK];
// split operands, layout [hi | lo], row stride 2K
__device__ __nv_bfloat16 g_a2[(size_t)TTOK*2*DINNER];
__device__ __nv_bfloat16 g_b2in[(size_t)INPROJ_PAD*2*DMODEL];
__device__ __nv_bfloat16 g_b2out[(size_t)DMODEL*2*DINNER];

// ---------------- helpers ----------------
__device__ __forceinline__ float block_reduce_sum_256(float v) {
    __shared__ float red[8];
    int lane = threadIdx.x & 31, w = threadIdx.x >> 5;
    #pragma unroll
    for (int o = 16; o; o >>= 1) v += __shfl_xor_sync(0xffffffffu, v, o);
    if (lane == 0) red[w] = v;
    __syncthreads();
    if (w == 0) {
        v = (lane < 8) ? red[lane] : 0.f;
        #pragma unroll
        for (int o = 4; o; o >>= 1) v += __shfl_xor_sync(0xffffffffu, v, o);
        if (lane == 0) red[0] = v;
    }
    __syncthreads();
    return red[0];
}

__device__ __forceinline__ unsigned int s2u(const void* p) {
    unsigned int a;
    asm("{ .reg .u64 t; cvta.to.shared.u64 t, %1; cvt.u32.u64 %0, t; }" : "=r"(a) : "l"(p));
    return a;
}

__device__ __forceinline__ void cpa16(unsigned int d, const void* g) {
    asm volatile("cp.async.cg.shared.global [%0], [%1], 16;\n" :: "r"(d), "l"(g));
}

// parallel inclusive scan of 256 values (one per thread)
__device__ __forceinline__ float scan256(float a, float* wps, float* tot) {
    int lane = threadIdx.x & 31, w = threadIdx.x >> 5;
    #pragma unroll
    for (int o = 1; o < 32; o <<= 1) {
        float t = __shfl_up_sync(0xffffffffu, a, o);
        if (lane >= o) a += t;
    }
    if (lane == 31) wps[w] = a;
    __syncthreads();
    if (threadIdx.x == 0) {
        float s = 0.f;
        #pragma unroll
        for (int j = 0; j < 8; j++) { float t = wps[j]; wps[j] = s; s += t; }
        wps[8] = s;
    }
    __syncthreads();
    float r = a + wps[w];
    *tot = wps[8];
    return r;
}

// ---------------- K1: input rmsnorm + bf16 split ([hi|lo]) --------------------
__global__ __launch_bounds__(256) void k_rms_in(const float* __restrict__ x,
                                                const float* __restrict__ w) {
    int row = blockIdx.x;
    const float* xr = x + (size_t)row * DMODEL;
    float vloc[8];
    float ss = 0.f;
    #pragma unroll
    for (int j = 0; j < 8; j++) { float v = xr[threadIdx.x + j * 256]; vloc[j] = v; ss += v * v; }
    float tot = block_reduce_sum_256(ss);
    float r = rsqrtf(tot * (1.f / DMODEL) + 1e-6f);
    size_t base = (size_t)row * (2 * DMODEL);
    #pragma unroll
    for (int j = 0; j < 8; j++) {
        int k = threadIdx.x + j * 256;
        float v = vloc[j] * r * w[k];
        __nv_bfloat16 hi = __float2bfloat16(v);
        __nv_bfloat16 lo = __float2bfloat16(v - __bfloat162float(hi));
        g_a2[base + k] = hi;
        g_a2[base + DMODEL + k] = lo;
    }
}

// ---------------- weight split conversion ([hi|lo]), 4 elems/thread -----------
__global__ __launch_bounds__(256) void k_cvt(int dsel, const float* __restrict__ srcp,
                                             int R, int K) {
    __nv_bfloat16* dst = (dsel == 1) ? g_b2in : g_b2out;
    int K4 = K >> 2;
    size_t idx = (size_t)blockIdx.x * 256 + threadIdx.x;
    int row = (int)(idx / K4);
    int k = (int)(idx - (size_t)row * K4) * 4;
    float4 v = (row < R) ? *(const float4*)&srcp[(size_t)row * K + k]
                         : make_float4(0.f, 0.f, 0.f, 0.f);
    __nv_bfloat16 hi[4], lo[4];
    float vv[4] = {v.x, v.y, v.z, v.w};
    #pragma unroll
    for (int j = 0; j < 4; j++) {
        hi[j] = __float2bfloat16(vv[j]);
        lo[j] = __float2bfloat16(vv[j] - __bfloat162float(hi[j]));
    }
    size_t base = (size_t)row * (2 * (size_t)K);
    *(uint2*)&dst[base + k]     = *(uint2*)hi;
    *(uint2*)&dst[base + K + k] = *(uint2*)lo;
}

// ---------------- bf16 tensor-core GEMM with fragment-reuse split -------------
// C[M,N] = sum over k of (Ahi+Alo)*(Bhi+Blo) dropping lo*lo.
// Operands stored [hi|lo] with row stride 2K; K here is the ORIGINAL depth.
#define HG_TILE  (128 * 40)
#define HG_STAGE (4 * HG_TILE)
#define HG_SMEM  (2 * HG_STAGE * 2)    // 81920 bytes

__global__ __launch_bounds__(256, 2) void k_hgemm(int selb, int selc,
        float* __restrict__ Cout,
        const float* __restrict__ addend, int M, int N, int K) {
    extern __shared__ __nv_bfloat16 smp[];
    const __nv_bfloat16* A2 = g_a2;
    const __nv_bfloat16* B2 = selb ? g_b2out : g_b2in;
    float* C = selc ? Cout : g_proj;
    int K2 = 2 * K;

    int tid = threadIdx.x, lane = tid & 31, warp = tid >> 5;
    int wm = warp >> 2, wn = warp & 3;
    int m0 = blockIdx.y * 128, n0 = blockIdx.x * 128;

    float acc[4][4][4];
    #pragma unroll
    for (int mi = 0; mi < 4; mi++)
        #pragma unroll
        for (int ni = 0; ni < 4; ni++)
            #pragma unroll
            for (int q = 0; q < 4; q++) acc[mi][ni][q] = 0.f;

    int nK = K >> 5;

    auto issue = [&](int kt, int st) {
        __nv_bfloat16* Ah = smp + st * HG_STAGE;
        __nv_bfloat16* Al = Ah + HG_TILE;
        __nv_bfloat16* Bh = Al + HG_TILE;
        __nv_bfloat16* Bl = Bh + HG_TILE;
        size_t kk = (size_t)kt * 32;
        #pragma unroll
        for (int i = 0; i < 2; i++) {
            int idx = tid + i * 256;
            int row = idx >> 2, c8 = (idx & 3) * 8;
            const __nv_bfloat16* ap = &A2[(size_t)(m0 + row) * K2 + kk + c8];
            const __nv_bfloat16* bp = &B2[(size_t)(n0 + row) * K2 + kk + c8];
            cpa16(s2u(&Ah[row * 40 + c8]), ap);
            cpa16(s2u(&Al[row * 40 + c8]), ap + K);
            cpa16(s2u(&Bh[row * 40 + c8]), bp);
            cpa16(s2u(&Bl[row * 40 + c8]), bp + K);
        }
        asm volatile("cp.async.commit_group;\n" ::);
    };

    issue(0, 0);

    for (int kt = 0; kt < nK; kt++) {
        int buf = kt & 1;
        if (kt + 1 < nK) {
            issue(kt + 1, (kt + 1) & 1);
            asm volatile("cp.async.wait_group 1;\n" ::);
        } else {
            asm volatile("cp.async.wait_group 0;\n" ::);
        }
        __syncthreads();

        const __nv_bfloat16* Ah = smp + buf * HG_STAGE;
        const __nv_bfloat16* Al = Ah + HG_TILE;
        const __nv_bfloat16* Bh = Al + HG_TILE;
        const __nv_bfloat16* Bl = Bh + HG_TILE;

        #pragma unroll
        for (int kh = 0; kh < 2; kh++) {
            unsigned int bh[4][2], bl[4][2];
            int bro = (wn * 32 + (lane & 7)) * 40 + kh * 16 + ((lane >> 3) & 1) * 8;
            #pragma unroll
            for (int ni = 0; ni < 4; ni++) {
                unsigned int addr = s2u(&Bh[bro + ni * 8 * 40]);
                asm volatile("ldmatrix.sync.aligned.m8n8.x2.shared.b16 {%0,%1}, [%2];"
                    : "=r"(bh[ni][0]), "=r"(bh[ni][1]) : "r"(addr));
                addr = s2u(&Bl[bro + ni * 8 * 40]);
                asm volatile("ldmatrix.sync.aligned.m8n8.x2.shared.b16 {%0,%1}, [%2];"
                    : "=r"(bl[ni][0]), "=r"(bl[ni][1]) : "r"(addr));
            }
            int aro = (wm * 64 + (lane & 15)) * 40 + kh * 16 + (lane >> 4) * 8;
            #pragma unroll
            for (int mi = 0; mi < 4; mi++) {
                unsigned int ah[4], al[4];
                unsigned int addr = s2u(&Ah[aro + mi * 16 * 40]);
                asm volatile("ldmatrix.sync.aligned.m8n8.x4.shared.b16 {%0,%1,%2,%3}, [%4];"
                    : "=r"(ah[0]), "=r"(ah[1]), "=r"(ah[2]), "=r"(ah[3]) : "r"(addr));
                #pragma unroll
                for (int ni = 0; ni < 4; ni++)
                    asm volatile("mma.sync.aligned.m16n8k16.row.col.f32.bf16.bf16.f32 "
                        "{%0,%1,%2,%3},{%4,%5,%6,%7},{%8,%9},{%0,%1,%2,%3};"
                        : "+f"(acc[mi][ni][0]), "+f"(acc[mi][ni][1]),
                          "+f"(acc[mi][ni][2]), "+f"(acc[mi][ni][3])
                        : "r"(ah[0]), "r"(ah[1]), "r"(ah[2]), "r"(ah[3]),
                          "r"(bh[ni][0]), "r"(bh[ni][1]));
                #pragma unroll
                for (int ni = 0; ni < 4; ni++)
                    asm volatile("mma.sync.aligned.m16n8k16.row.col.f32.bf16.bf16.f32 "
                        "{%0,%1,%2,%3},{%4,%5,%6,%7},{%8,%9},{%0,%1,%2,%3};"
                        : "+f"(acc[mi][ni][0]), "+f"(acc[mi][ni][1]),
                          "+f"(acc[mi][ni][2]), "+f"(acc[mi][ni][3])
                        : "r"(ah[0]), "r"(ah[1]), "r"(ah[2]), "r"(ah[3]),
                          "r"(bl[ni][0]), "r"(bl[ni][1]));
                addr = s2u(&Al[aro + mi * 16 * 40]);
                asm volatile("ldmatrix.sync.aligned.m8n8.x4.shared.b16 {%0,%1,%2,%3}, [%4];"
                    : "=r"(al[0]), "=r"(al[1]), "=r"(al[2]), "=r"(al[3]) : "r"(addr));
                #pragma unroll
                for (int ni = 0; ni < 4; ni++)
                    asm volatile("mma.sync.aligned.m16n8k16.row.col.f32.bf16.bf16.f32 "
                        "{%0,%1,%2,%3},{%4,%5,%6,%7},{%8,%9},{%0,%1,%2,%3};"
                        : "+f"(acc[mi][ni][0]), "+f"(acc[mi][ni][1]),
                          "+f"(acc[mi][ni][2]), "+f"(acc[mi][ni][3])
                        : "r"(al[0]), "r"(al[1]), "r"(al[2]), "r"(al[3]),
                          "r"(bh[ni][0]), "r"(bh[ni][1]));
            }
        }
        __syncthreads();
    }

    // epilogue: paired float2 access (N even; cc even => cc<N implies cc+1<N)
    #pragma unroll
    for (int mi = 0; mi < 4; mi++) {
        int r = m0 + wm * 64 + mi * 16 + (lane >> 2);
        #pragma unroll
        for (int ni = 0; ni < 4; ni++) {
            int cc = n0 + wn * 32 + ni * 8 + (lane & 3) * 2;
            if (cc < N) {
                #pragma unroll
                for (int half = 0; half < 2; half++) {
                    int rr = r + half * 8;
                    float2 v = make_float2(acc[mi][ni][half * 2], acc[mi][ni][half * 2 + 1]);
                    if (addend) {
                        float2 a = *(const float2*)&addend[(size_t)rr * N + cc];
                        v.x += a.x; v.y += a.y;
                    }
                    *(float2*)&C[(size_t)rr * N + cc] = v;
                }
            }
        }
    }
}

// ---------------- K3: depthwise conv4 + bias + rmsnorm + silu ----------------
// scalar channel-per-thread layout (coalesced); float4 tap fetch; l>=3 fast path
__global__ __launch_bounds__(256) void k_conv(const float* __restrict__ cw,
        const float* __restrict__ cb, const float* __restrict__ cnw) {
    int t = blockIdx.x;
    int b = t >> 11, l = t & 2047;
    float v[24];
    float ss = 0.f;
    if (l >= 3) {
        const float* p0 = &g_proj[(size_t)(b * LSEQ + l - 3) * INPROJ];
        #pragma unroll
        for (int j = 0; j < 24; j++) {
            int c = threadIdx.x + j * 256;
            int pc = (c < DINNER) ? c : c + NHEAD;
            float4 wv = *(const float4*)&cw[c * 4];
            float a = cb[c];
            a += wv.x * p0[pc];
            a += wv.y * p0[INPROJ + pc];
            a += wv.z * p0[2 * INPROJ + pc];
            a += wv.w * p0[3 * INPROJ + pc];
            v[j] = a;
            ss += a * a;
        }
    } else {
        #pragma unroll
        for (int j = 0; j < 24; j++) {
            int c = threadIdx.x + j * 256;
            int pc = (c < DINNER) ? c : c + NHEAD;
            float4 wv = *(const float4*)&cw[c * 4];
            float wk[4] = {wv.x, wv.y, wv.z, wv.w};
            float a = cb[c];
            #pragma unroll
            for (int k = 0; k < 4; k++) {
                int lk = l + k - 3;
                if (lk >= 0)
                    a += wk[k] * g_proj[(size_t)(b * LSEQ + lk) * INPROJ + pc];
            }
            v[j] = a;
            ss += a * a;
        }
    }
    float tot = block_reduce_sum_256(ss);
    float r = rsqrtf(tot * (1.f / CONVDIM) + 1e-6f);
    #pragma unroll
    for (int j = 0; j < 24; j++) {
        int c = threadIdx.x + j * 256;
        float y = v[j] * r * cnw[c];
        g_conv[(size_t)t * CONVDIM + c] = y / (1.f + expf(-y));
    }
}

// ---------------- K4: dt path ----------------
__global__ __launch_bounds__(256) void k_dt(const float* __restrict__ dt_w,
        const float* __restrict__ dt_b, const float* __restrict__ A_log) {
    __shared__ float ad[4][64];
    int sub = threadIdx.x >> 6, h = threadIdx.x & 63;
    int t = blockIdx.x * 4 + sub;
    ad[sub][h] = g_proj[(size_t)t * INPROJ + COL_ADT + h];
    __syncthreads();
    float z = dt_b[h];
    #pragma unroll
    for (int k = 0; k < 64; k++) z += ad[sub][k] * dt_w[h * 64 + k];
    float dt = (z > 20.f) ? z : log1pf(expf(z));
    g_A[(size_t)t * NHEAD + h] = -expf(A_log[h]) * dt;
}

// ---------------- K5: per-chunk states ----------------------------------------
__global__ __launch_bounds__(256) void k_states() {
    __shared__ __align__(16) float sB[32 * 128];
    __shared__ __align__(16) float sX[32 * 64];
    __shared__ float sw[256];
    __shared__ float wps[9];
    int blk = blockIdx.x;
    int b = blk >> 9, c = (blk >> 6) & 7, h = blk & 63, g = h >> 3;
    int tid = threadIdx.x;
    size_t tokbase = (size_t)(b * LSEQ + c * CHUNK);

    float av = g_A[(tokbase + tid) * NHEAD + h];
    float atot;
    float acs = scan256(av, wps, &atot);
    sw[tid] = expf(atot - acs);
    if (tid == 0) g_Alast[blk] = atot;
    __syncthreads();

    int n = tid >> 1, dh = tid & 1, db = dh << 5;
    float acc[32];
    #pragma unroll
    for (int j = 0; j < 32; j++) acc[j] = 0.f;

    for (int t0 = 0; t0 < 256; t0 += 32) {
        __syncthreads();
        #pragma unroll
        for (int k = 0; k < 4; k++) {
            int q = tid + k * 256; int j = q >> 5, n4 = (q & 31) << 2;
            *(float4*)&sB[j * 128 + n4] =
                *(const float4*)&g_conv[(tokbase + t0 + j) * CONVDIM + CCOL_B + g * 128 + n4];
        }
        #pragma unroll
        for (int k = 0; k < 2; k++) {
            int q = tid + k * 256; int j = q >> 4, d4 = (q & 15) << 2;
            *(float4*)&sX[j * 64 + d4] =
                *(const float4*)&g_conv[(tokbase + t0 + j) * CONVDIM + h * 64 + d4];
        }
        __syncthreads();
        #pragma unroll
        for (int i = 0; i < 32; i++) {
            float bw = sB[i * 128 + n] * sw[t0 + i];
            const float4* xr = (const float4*)&sX[i * 64 + db];
            #pragma unroll
            for (int j = 0; j < 8; j++) {
                float4 xv = xr[j];
                acc[4 * j + 0] += bw * xv.x;
                acc[4 * j + 1] += bw * xv.y;
                acc[4 * j + 2] += bw * xv.z;
                acc[4 * j + 3] += bw * xv.w;
            }
        }
    }
    size_t ob = ((size_t)blk * NSTATE + n) * DHEAD + db;
    #pragma unroll
    for (int j = 0; j < 8; j++)
        *(float4*)&g_states[ob + 4 * j] =
            make_float4(acc[4 * j], acc[4 * j + 1], acc[4 * j + 2], acc[4 * j + 3]);
}

// ---------------- K6: inter-chunk scan -----------------------------------------
__global__ __launch_bounds__(256) void k_scan(float* __restrict__ hout) {
    int b = blockIdx.x >> 6, h = blockIdx.x & 63;
    int e0 = threadIdx.x * 32;
    float hs[32];
    #pragma unroll
    for (int j = 0; j < 32; j++) hs[j] = 0.f;
    for (int c = 0; c < NCHUNK; c++) {
        int chb = (b * NCHUNK + c) * NHEAD + h;
        float cd = expf(g_Alast[chb]);
        size_t base = (size_t)chb * (NSTATE * DHEAD) + e0;
        #pragma unroll
        for (int j = 0; j < 8; j++) {
            *(float4*)&g_hprev[base + 4 * j] =
                make_float4(hs[4 * j], hs[4 * j + 1], hs[4 * j + 2], hs[4 * j + 3]);
            float4 st = *(const float4*)&g_states[base + 4 * j];
            hs[4 * j + 0] = hs[4 * j + 0] * cd + st.x;
            hs[4 * j + 1] = hs[4 * j + 1] * cd + st.y;
            hs[4 * j + 2] = hs[4 * j + 2] * cd + st.z;
            hs[4 * j + 3] = hs[4 * j + 3] * cd + st.w;
        }
    }
    if (hout) {
        size_t ob = (size_t)(b * NHEAD + h) * (NSTATE * DHEAD) + e0;
        #pragma unroll
        for (int j = 0; j < 8; j++)
            *(float4*)&hout[ob + 4 * j] =
                make_float4(hs[4 * j], hs[4 * j + 1], hs[4 * j + 2], hs[4 * j + 3]);
    }
}

// ---------------- K-CB: per-(b,c,g) raw CB = C @ B^T (tril tiles) --------------
__global__ __launch_bounds__(256) void k_cb() {
    __shared__ __align__(16) float sCt[32][128];
    __shared__ __align__(16) float sB[32 * 133];
    int blk = blockIdx.x;
    int b = blk >> 6, c = (blk >> 3) & 7, g = blk & 7;
    int tid = threadIdx.x;
    size_t tokbase = (size_t)(b * LSEQ + c * CHUNK);
    size_t cbbase = (size_t)blk * (CHUNK * CHUNK);
    int bi = tid >> 4, bj = tid & 15;

    for (int t0 = 0; t0 < 8; t0++) {
        __syncthreads();
        #pragma unroll
        for (int k = 0; k < 4; k++) {
            int q = tid + k * 256; int i = q >> 5, n4 = (q & 31) << 2;
            *(float4*)&sCt[i][n4] =
                *(const float4*)&g_conv[(tokbase + t0 * 32 + i) * CONVDIM + CCOL_C + g * 128 + n4];
        }
        for (int s0 = 0; s0 <= t0; s0++) {
            __syncthreads();
            #pragma unroll
            for (int k = 0; k < 4; k++) {
                int q = tid + k * 256; int j = q >> 5, n4 = (q & 31) << 2;
                float4 v = *(const float4*)&g_conv[(tokbase + s0 * 32 + j) * CONVDIM + CCOL_B + g * 128 + n4];
                sB[j * 133 + n4 + 0] = v.x;
                sB[j * 133 + n4 + 1] = v.y;
                sB[j * 133 + n4 + 2] = v.z;
                sB[j * 133 + n4 + 3] = v.w;
            }
            __syncthreads();
            float m00 = 0.f, m01 = 0.f, m10 = 0.f, m11 = 0.f;
            const float* c0p = &sCt[2 * bi][0];
            const float* c1p = &sCt[2 * bi + 1][0];
            const float* b0p = &sB[(2 * bj) * 133];
            const float* b1p = &sB[(2 * bj + 1) * 133];
            #pragma unroll 8
            for (int n = 0; n < 128; n++) {
                float c0 = c0p[n], c1 = c1p[n], bb0 = b0p[n], bb1 = b1p[n];
                m00 += c0 * bb0; m01 += c0 * bb1;
                m10 += c1 * bb0; m11 += c1 * bb1;
            }
            size_t r0 = cbbase + (size_t)(t0 * 32 + 2 * bi) * CHUNK + s0 * 32 + 2 * bj;
            *(float2*)&g_CB[r0] = make_float2(m00, m01);
            *(float2*)&g_CB[r0 + CHUNK] = make_float2(m10, m11);
        }
    }
}

// ---------------- K7: Y = Y_diag + Y_carry (CB from global; R14 version) ------
__global__ __launch_bounds__(256) void k_ydiag() {
    __shared__ float sAcs[256];
    __shared__ float wps[9];
    __shared__ __align__(16) float sCtT[128][36];
    __shared__ __align__(16) float sM[32][36];
    __shared__ __align__(16) float sX[32][64];
    __shared__ __align__(16) float sH[32 * 64];
    __shared__ float fr[32];
    __shared__ float gc[256];
    int blk = blockIdx.x;
    int b = blk >> 9, c = (blk >> 6) & 7, h = blk & 63, g = h >> 3;
    int tid = threadIdx.x;
    size_t tokbase = (size_t)(b * LSEQ + c * CHUNK);
    size_t chb = (size_t)blk;
    size_t cbbase = (size_t)(((b * 8 + c) * 8) + g) * (CHUNK * CHUNK);

    {
        float av = g_A[(tokbase + tid) * NHEAD + h];
        float atot;
        float acs = scan256(av, wps, &atot);
        sAcs[tid] = acs;
    }
    __syncthreads();

    int ty = tid >> 5, tx = tid & 31;
    int bi = tid >> 4, bj = tid & 15;

    for (int t0 = 0; t0 < 8; t0++) {
        __syncthreads();
        #pragma unroll
        for (int k = 0; k < 4; k++) {
            int q = tid + k * 256;
            int chunk = q >> 5, i = q & 31;
            float4 v = *(const float4*)&g_conv[(tokbase + t0 * 32 + i) * CONVDIM + CCOL_C + g * 128 + chunk * 4];
            sCtT[chunk * 4 + 0][i] = v.x;
            sCtT[chunk * 4 + 1][i] = v.y;
            sCtT[chunk * 4 + 2][i] = v.z;
            sCtT[chunk * 4 + 3][i] = v.w;
        }
        float ar = sAcs[t0 * 32];
        if (tid < 32) fr[tid] = expf(sAcs[t0 * 32 + tid] - ar);
        if (tid < t0 * 32) gc[tid] = expf(ar - sAcs[tid]);
        __syncthreads();

        float accD[4][2] = {{0.f,0.f},{0.f,0.f},{0.f,0.f},{0.f,0.f}};
        float acc2[4][2] = {{0.f,0.f},{0.f,0.f},{0.f,0.f},{0.f,0.f}};

        for (int s0 = 0; s0 <= t0; s0++) {
            #pragma unroll
            for (int k = 0; k < 2; k++) {
                int q = tid + k * 256; int j = q >> 4, d4 = (q & 15) << 2;
                *(float4*)&sX[j][d4] =
                    *(const float4*)&g_conv[(tokbase + s0 * 32 + j) * CONVDIM + h * 64 + d4];
            }
            {
                int i0 = 2 * bi, j0 = 2 * bj;
                size_t r0 = cbbase + (size_t)(t0 * 32 + i0) * CHUNK + s0 * 32 + j0;
                float2 m0 = *(const float2*)&g_CB[r0];
                float2 m1 = *(const float2*)&g_CB[r0 + CHUNK];
                if (s0 < t0) {
                    float f0 = fr[i0], f1 = fr[i0 + 1];
                    float g0 = gc[s0 * 32 + j0], g1 = gc[s0 * 32 + j0 + 1];
                    sM[j0][i0]         = m0.x * f0 * g0;
                    sM[j0 + 1][i0]     = m0.y * f0 * g1;
                    sM[j0][i0 + 1]     = m1.x * f1 * g0;
                    sM[j0 + 1][i0 + 1] = m1.y * f1 * g1;
                } else {
                    float at0 = sAcs[t0 * 32 + i0], at1 = sAcs[t0 * 32 + i0 + 1];
                    float as0 = sAcs[s0 * 32 + j0], as1 = sAcs[s0 * 32 + j0 + 1];
                    sM[j0][i0]         = (j0     <= i0    ) ? m0.x * expf(at0 - as0) : 0.f;
                    sM[j0 + 1][i0]     = (j0 + 1 <= i0    ) ? m0.y * expf(at0 - as1) : 0.f;
                    sM[j0][i0 + 1]     = (j0     <= i0 + 1) ? m1.x * expf(at1 - as0) : 0.f;
                    sM[j0 + 1][i0 + 1] = (j0 + 1 <= i0 + 1) ? m1.y * expf(at1 - as1) : 0.f;
                }
            }
            __syncthreads();
            #pragma unroll
            for (int k = 0; k < 32; k++) {
                float4 mv = *(const float4*)&sM[k][4 * ty];
                float2 xv = *(const float2*)&sX[k][2 * tx];
                accD[0][0] += mv.x * xv.x; accD[0][1] += mv.x * xv.y;
                accD[1][0] += mv.y * xv.x; accD[1][1] += mv.y * xv.y;
                accD[2][0] += mv.z * xv.x; accD[2][1] += mv.z * xv.y;
                accD[3][0] += mv.w * xv.x; accD[3][1] += mv.w * xv.y;
            }
            __syncthreads();
        }
        for (int qh = 0; qh < 4; qh++) {
            #pragma unroll
            for (int k = 0; k < 2; k++) {
                int q = tid + k * 256; int nl = q >> 4, d4 = (q & 15) << 2;
                *(float4*)&sH[nl * 64 + d4] =
                    *(const float4*)&g_hprev[(chb * NSTATE + qh * 32 + nl) * DHEAD + d4];
            }
            __syncthreads();
            #pragma unroll
            for (int k = 0; k < 32; k++) {
                int n = qh * 32 + k;
                float4 cv = *(const float4*)&sCtT[n][4 * ty];
                float2 hv = *(const float2*)&sH[k * 64 + 2 * tx];
                acc2[0][0] += cv.x * hv.x; acc2[0][1] += cv.x * hv.y;
                acc2[1][0] += cv.y * hv.x; acc2[1][1] += cv.y * hv.y;
                acc2[2][0] += cv.z * hv.x; acc2[2][1] += cv.z * hv.y;
                acc2[3][0] += cv.w * hv.x; acc2[3][1] += cv.w * hv.y;
            }
            __syncthreads();
        }
        #pragma unroll
        for (int r = 0; r < 4; r++) {
            int t = t0 * 32 + 4 * ty + r;
            float e = expf(sAcs[t]);
            size_t off = (tokbase + t) * DINNER + h * 64 + 2 * tx;
            g_Y[off]     = accD[r][0] + acc2[r][0] * e;
            g_Y[off + 1] = accD[r][1] + acc2[r][1] * e;
        }
    }
}

// ---------------- K8: out rmsnorm * silu(gate) -> bf16 split into g_a2 --------
__global__ __launch_bounds__(256) void k_gate(const float* __restrict__ onw) {
    int t = blockIdx.x;
    float vloc[16];
    float ss = 0.f;
    #pragma unroll
    for (int j = 0; j < 16; j++) {
        float v = g_Y[(size_t)t * DINNER + threadIdx.x + j * 256];
        vloc[j] = v;
        ss += v * v;
    }
    float tot = block_reduce_sum_256(ss);
    float r = rsqrtf(tot * (1.f / DINNER) + 1e-6f);
    size_t base = (size_t)t * (2 * DINNER);
    #pragma unroll
    for (int j = 0; j < 16; j++) {
        int k = threadIdx.x + j * 256;
        float y = vloc[j] * r * onw[k];
        float gt = g_proj[(size_t)t * INPROJ + COL_GATE + k];
        float v = y * gt / (1.f + expf(-gt));
        __nv_bfloat16 hi = __float2bfloat16(v);
        __nv_bfloat16 lo = __float2bfloat16(v - __bfloat162float(hi));
        g_a2[base + k] = hi;
        g_a2[base + DINNER + k] = lo;
    }
}

// ---------------- launch ----------------
extern "C" void kernel_launch(void* const* d_in, const int* in_sizes, int n_in,
                              void* d_out, int out_size) {
    const float* x          = (const float*)d_in[0];
    const float* norm_w     = (const float*)d_in[1];
    const float* in_proj_w  = (const float*)d_in[2];
    const float* conv_w     = (const float*)d_in[3];
    const float* conv_b     = (const float*)d_in[4];
    const float* conv_norm_w= (const float*)d_in[5];
    const float* A_log      = (const float*)d_in[6];
    const float* dt_w       = (const float*)d_in[7];
    const float* dt_b       = (const float*)d_in[8];
    const float* out_norm_w = (const float*)d_in[9];
    const float* out_proj_w = (const float*)d_in[10];
    float* out = (float*)d_out;

    float* hfin = (out_size >= OUT_ELEMS + HFIN_ELEMS) ? (out + OUT_ELEMS) : nullptr;

    cudaFuncSetAttribute(k_hgemm, cudaFuncAttributeMaxDynamicSharedMemorySize, HG_SMEM);

    k_rms_in<<<TTOK, 256>>>(x, norm_w);
    k_cvt<<<(unsigned)(((size_t)INPROJ_PAD * DMODEL) / 1024), 256>>>(1, in_proj_w, INPROJ, DMODEL);
    k_hgemm<<<dim3(INPROJ_PAD / 128, TTOK / 128), 256, HG_SMEM>>>(
        0, 0, nullptr, nullptr, TTOK, INPROJ, DMODEL);

    k_conv<<<TTOK, 256>>>(conv_w, conv_b, conv_norm_w);
    k_dt<<<TTOK / 4, 256>>>(dt_w, dt_b, A_log);
    k_cb<<<Bb * NCHUNK * NGRP, 256>>>();
    k_states<<<Bb * NCHUNK * NHEAD, 256>>>();
    k_scan<<<Bb * NHEAD, 256>>>(hfin);
    k_ydiag<<<Bb * NCHUNK * NHEAD, 256>>>();
    k_gate<<<TTOK, 256>>>(out_norm_w);

    k_cvt<<<(unsigned)(((size_t)DMODEL * DINNER) / 1024), 256>>>(2, out_proj_w, DMODEL, DINNER);
    k_hgemm<<<dim3(DMODEL / 128, TTOK / 128), 256, HG_SMEM>>>(
        1, 1, out, x, TTOK, DMODEL, DINNER);
}